// round 3
// baseline (speedup 1.0000x reference)
#include <cuda_runtime.h>

typedef unsigned long long u64;

#define NMAX 50048
#define EMAX 1600000

__device__ int   g_deg[NMAX];
__device__ int   g_off[NMAX + 1];
__device__ int   g_cur[NMAX];
__device__ int   g_bsum[64];
__device__ int   g_ssrc[EMAX];
__device__ float g_P[(size_t)NMAX * 128];
__device__ float g_Q[(size_t)NMAX * 128];
__device__ float g_H[(size_t)NMAX * 128];

__device__ __forceinline__ u64 pack2f(float lo, float hi) {
    u64 r; asm("mov.b64 %0, {%1, %2};" : "=l"(r) : "f"(lo), "f"(hi)); return r;
}
__device__ __forceinline__ float2 unpack2f(u64 v) {
    float2 f; asm("mov.b64 {%0, %1}, %2;" : "=f"(f.x), "=f"(f.y) : "l"(v)); return f;
}
__device__ __forceinline__ u64 ffma2(u64 a, u64 b, u64 c) {
    u64 d; asm("fma.rn.f32x2 %0, %1, %2, %3;" : "=l"(d) : "l"(a), "l"(b), "l"(c)); return d;
}

// ---------------- CSR build ----------------

__global__ void k_zero(int N) {
    int i = blockIdx.x * blockDim.x + threadIdx.x;
    if (i < N) g_deg[i] = 0;
}

__global__ void k_hist(const int* __restrict__ dst, int E) {
    int i = blockIdx.x * blockDim.x + threadIdx.x;
    if (i < E) atomicAdd(&g_deg[dst[i]], 1);
}

__global__ void k_scan_a(int N) {
    int idx = blockIdx.x * 1024 + threadIdx.x;
    int v = (idx < N) ? g_deg[idx] : 0;
    #pragma unroll
    for (int d = 16; d > 0; d >>= 1) v += __shfl_down_sync(0xffffffffu, v, d);
    __shared__ int ws[32];
    if ((threadIdx.x & 31) == 0) ws[threadIdx.x >> 5] = v;
    __syncthreads();
    if (threadIdx.x < 32) {
        int s = ws[threadIdx.x];
        #pragma unroll
        for (int d = 16; d > 0; d >>= 1) s += __shfl_down_sync(0xffffffffu, s, d);
        if (threadIdx.x == 0) g_bsum[blockIdx.x] = s;
    }
}

__global__ void k_scan_b(int nb) {
    if (threadIdx.x == 0 && blockIdx.x == 0) {
        int run = 0;
        for (int i = 0; i < nb; ++i) { int t = g_bsum[i]; g_bsum[i] = run; run += t; }
    }
}

__global__ void k_scan_c(int N) {
    int idx = blockIdx.x * 1024 + threadIdx.x;
    int lane = threadIdx.x & 31, wid = threadIdx.x >> 5;
    int v = (idx < N) ? g_deg[idx] : 0;
    int val = v;
    #pragma unroll
    for (int d = 1; d < 32; d <<= 1) {
        int t = __shfl_up_sync(0xffffffffu, val, d);
        if (lane >= d) val += t;
    }
    __shared__ int ws[32];
    if (lane == 31) ws[wid] = val;
    __syncthreads();
    if (wid == 0) {
        int s = ws[lane];
        #pragma unroll
        for (int d = 1; d < 32; d <<= 1) {
            int t = __shfl_up_sync(0xffffffffu, s, d);
            if (lane >= d) s += t;
        }
        ws[lane] = s;
    }
    __syncthreads();
    int base = g_bsum[blockIdx.x] + (wid ? ws[wid - 1] : 0);
    int excl = base + val - v;
    if (idx < N) { g_off[idx] = excl; g_cur[idx] = excl; }
    if (idx == N - 1) g_off[N] = excl + v;
}

__global__ void k_scatter(const int* __restrict__ src, const int* __restrict__ dst, int E) {
    int i = blockIdx.x * blockDim.x + threadIdx.x;
    if (i < E) {
        int pos = atomicAdd(&g_cur[dst[i]], 1);
        g_ssrc[pos] = src[i];
    }
}

// ---------------- Node input transform: P = h@(W1a-W1b)+b1, Q = h@W1b ----------------
// 128 threads (thread = output col c), 8 nodes per tile, f32x2 k-pair packing.

__global__ void k_node(const float* __restrict__ x, const float* __restrict__ sc,
                       const int* __restrict__ batch, const float* __restrict__ W1,
                       const float* __restrict__ b1, int N) {
    extern __shared__ char smem[];
    u64* Wdp = (u64*)smem;                 // 34*128 packed k-pairs of (W1a - W1b)
    u64* Wbp = Wdp + 34 * 128;             // 34*128 packed k-pairs of W1b
    float* hs = (float*)(Wbp + 34 * 128);  // 8 nodes * 68 feats
    float* b1s = hs + 8 * 68;              // 128
    int tid = threadIdx.x;                 // 128 threads

    for (int i = tid; i < 34 * 128; i += 128) {
        int kp = i >> 7, c = i & 127;
        float a0 = W1[(2 * kp) * 128 + c];
        float a1 = W1[(2 * kp + 1) * 128 + c];
        float q0 = W1[(68 + 2 * kp) * 128 + c];
        float q1 = W1[(68 + 2 * kp + 1) * 128 + c];
        Wdp[i] = pack2f(a0 - q0, a1 - q1);
        Wbp[i] = pack2f(q0, q1);
    }
    b1s[tid] = b1[tid];
    __syncthreads();

    int c = tid;
    int ntiles = (N + 7) >> 3;
    for (int tile = blockIdx.x; tile < ntiles; tile += gridDim.x) {
        int n0 = tile << 3;
        for (int i = tid; i < 8 * 68; i += 128) {
            int nn = i / 68, k = i - nn * 68;
            int n = n0 + nn;
            float v = 0.f;
            if (n < N) v = (k < 64) ? x[(size_t)n * 64 + k] : sc[batch[n] * 4 + (k - 64)];
            hs[i] = v;
        }
        __syncthreads();
        u64 accP[8], accQ[8];
        #pragma unroll
        for (int nn = 0; nn < 8; ++nn) {
            accP[nn] = pack2f(b1s[c], 0.f);
            accQ[nn] = pack2f(0.f, 0.f);
        }
        #pragma unroll
        for (int k = 0; k < 68; k += 4) {
            int kp = k >> 1;
            u64 wd0 = Wdp[kp * 128 + c], wd1 = Wdp[(kp + 1) * 128 + c];
            u64 wb0 = Wbp[kp * 128 + c], wb1 = Wbp[(kp + 1) * 128 + c];
            #pragma unroll
            for (int nn = 0; nn < 8; ++nn) {
                ulonglong2 hh = *(const ulonglong2*)(hs + nn * 68 + k);
                accP[nn] = ffma2(wd0, hh.x, accP[nn]);
                accQ[nn] = ffma2(wb0, hh.x, accQ[nn]);
                accP[nn] = ffma2(wd1, hh.y, accP[nn]);
                accQ[nn] = ffma2(wb1, hh.y, accQ[nn]);
            }
        }
        #pragma unroll
        for (int nn = 0; nn < 8; ++nn) {
            int n = n0 + nn;
            if (n < N) {
                float2 fp = unpack2f(accP[nn]);
                float2 fq = unpack2f(accQ[nn]);
                g_P[(size_t)n * 128 + c] = fp.x + fp.y;
                g_Q[(size_t)n * 128 + c] = fq.x + fq.y;
            }
        }
        __syncthreads();
    }
}

// ---------------- Edge aggregation: H[n] = sum_{e:dst=n} relu(P[n] + Q[src_e]) ----------------
// One warp per node; lane l owns cols 4l..4l+3 (float4). Pure gather from L2-resident Q.

__global__ void k_edge(int N) {
    int gw = (blockIdx.x * blockDim.x + threadIdx.x) >> 5;
    int lane = threadIdx.x & 31;
    if (gw >= N) return;
    int beg = g_off[gw], end = g_off[gw + 1];
    float4 p = *(const float4*)(g_P + (size_t)gw * 128 + lane * 4);
    float4 acc = make_float4(0.f, 0.f, 0.f, 0.f);
    for (int base = beg; base < end; base += 32) {
        int m = end - base; if (m > 32) m = 32;
        int myj = (lane < m) ? g_ssrc[base + lane] : 0;
        if (m == 32) {
            #pragma unroll 4
            for (int t = 0; t < 32; ++t) {
                int j = __shfl_sync(0xffffffffu, myj, t);
                float4 q = *(const float4*)(g_Q + (size_t)j * 128 + lane * 4);
                acc.x += fmaxf(p.x + q.x, 0.f);
                acc.y += fmaxf(p.y + q.y, 0.f);
                acc.z += fmaxf(p.z + q.z, 0.f);
                acc.w += fmaxf(p.w + q.w, 0.f);
            }
        } else {
            for (int t = 0; t < m; ++t) {
                int j = __shfl_sync(0xffffffffu, myj, t);
                float4 q = *(const float4*)(g_Q + (size_t)j * 128 + lane * 4);
                acc.x += fmaxf(p.x + q.x, 0.f);
                acc.y += fmaxf(p.y + q.y, 0.f);
                acc.z += fmaxf(p.z + q.z, 0.f);
                acc.w += fmaxf(p.w + q.w, 0.f);
            }
        }
    }
    *(float4*)(g_H + (size_t)gw * 128 + lane * 4) = acc;
}

// ---------------- Output GEMM: out = H @ W2 + deg*b2 ----------------

__global__ void k_out(const float* __restrict__ W2, const float* __restrict__ b2,
                      float* __restrict__ out, int N) {
    extern __shared__ char smem[];
    u64* W2p = (u64*)smem;                 // 64*128 packed k-pairs
    float* hs = (float*)(W2p + 64 * 128);  // 8 nodes * 128
    float* b2s = hs + 8 * 128;             // 128
    int tid = threadIdx.x;                 // 128 threads

    for (int i = tid; i < 64 * 128; i += 128) {
        int kp = i >> 7, c = i & 127;
        W2p[i] = pack2f(W2[(2 * kp) * 128 + c], W2[(2 * kp + 1) * 128 + c]);
    }
    b2s[tid] = b2[tid];
    __syncthreads();

    int c = tid;
    int ntiles = (N + 7) >> 3;
    for (int tile = blockIdx.x; tile < ntiles; tile += gridDim.x) {
        int n0 = tile << 3;
        for (int i = tid; i < 8 * 128; i += 128) {
            int nn = i >> 7, cc = i & 127;
            int n = n0 + nn;
            hs[i] = (n < N) ? g_H[(size_t)n * 128 + cc] : 0.f;
        }
        __syncthreads();
        u64 acc[8];
        #pragma unroll
        for (int nn = 0; nn < 8; ++nn) acc[nn] = pack2f(0.f, 0.f);
        #pragma unroll
        for (int k = 0; k < 128; k += 4) {
            int kp = k >> 1;
            u64 w0 = W2p[kp * 128 + c], w1 = W2p[(kp + 1) * 128 + c];
            #pragma unroll
            for (int nn = 0; nn < 8; ++nn) {
                ulonglong2 hh = *(const ulonglong2*)(hs + nn * 128 + k);
                acc[nn] = ffma2(w0, hh.x, acc[nn]);
                acc[nn] = ffma2(w1, hh.y, acc[nn]);
            }
        }
        #pragma unroll
        for (int nn = 0; nn < 8; ++nn) {
            int n = n0 + nn;
            if (n < N) {
                float2 f = unpack2f(acc[nn]);
                float deg = (float)(g_off[n + 1] - g_off[n]);
                out[(size_t)n * 128 + c] = f.x + f.y + deg * b2s[c];
            }
        }
        __syncthreads();
    }
}

// ---------------- launch ----------------

extern "C" void kernel_launch(void* const* d_in, const int* in_sizes, int n_in,
                              void* d_out, int out_size) {
    const float* x   = (const float*)d_in[0];
    const float* sc  = (const float*)d_in[1];
    const int* batch = (const int*)d_in[2];
    const int* ei    = (const int*)d_in[3];
    const float* W1  = (const float*)d_in[4];
    const float* b1  = (const float*)d_in[5];
    const float* W2  = (const float*)d_in[6];
    const float* b2  = (const float*)d_in[7];
    float* out = (float*)d_out;
    int N = in_sizes[0] / 64;
    int E = in_sizes[3] / 2;
    const int* src = ei;        // edge_index[0]
    const int* dst = ei + E;    // edge_index[1]

    const int smem_node = 2 * 34 * 128 * 8 + 8 * 68 * 4 + 128 * 4;   // 72320 B
    const int smem_out  = 64 * 128 * 8 + 8 * 128 * 4 + 128 * 4;      // 70144 B
    cudaFuncSetAttribute(k_node, cudaFuncAttributeMaxDynamicSharedMemorySize, smem_node);
    cudaFuncSetAttribute(k_out,  cudaFuncAttributeMaxDynamicSharedMemorySize, smem_out);

    int nb = (N + 1023) >> 10;
    k_zero<<<(N + 255) / 256, 256>>>(N);
    k_hist<<<(E + 255) / 256, 256>>>(dst, E);
    k_scan_a<<<nb, 1024>>>(N);
    k_scan_b<<<1, 32>>>(nb);
    k_scan_c<<<nb, 1024>>>(N);
    k_scatter<<<(E + 255) / 256, 256>>>(src, dst, E);
    k_node<<<296, 128, smem_node>>>(x, sc, batch, W1, b1, N);
    k_edge<<<(N + 7) / 8, 256>>>(N);
    k_out<<<444, 128, smem_out>>>(W2, b2, out, N);
}

// round 6
// speedup vs baseline: 1.0429x; 1.0429x over previous
#include <cuda_runtime.h>
#include <cuda_fp16.h>

typedef unsigned long long u64;

#define NMAX 50048
#define EMAX 1600000

__device__ int    g_deg[NMAX];
__device__ int    g_off[NMAX + 1];
__device__ int    g_cur[NMAX];
__device__ int    g_bsum[64];
__device__ int    g_ssrc[EMAX];
__device__ __half g_Ph[(size_t)NMAX * 128];
__device__ __half g_Qh[(size_t)NMAX * 128];
__device__ float  g_H[(size_t)NMAX * 128];

__device__ __forceinline__ u64 pack2f(float lo, float hi) {
    u64 r; asm("mov.b64 %0, {%1, %2};" : "=l"(r) : "f"(lo), "f"(hi)); return r;
}
__device__ __forceinline__ float2 unpack2f(u64 v) {
    float2 f; asm("mov.b64 {%0, %1}, %2;" : "=f"(f.x), "=f"(f.y) : "l"(v)); return f;
}
__device__ __forceinline__ u64 ffma2(u64 a, u64 b, u64 c) {
    u64 d; asm("fma.rn.f32x2 %0, %1, %2, %3;" : "=l"(d) : "l"(a), "l"(b), "l"(c)); return d;
}

// ---------------- CSR build ----------------

__global__ void k_hist(const int* __restrict__ dst, int E) {
    int i = blockIdx.x * blockDim.x + threadIdx.x;
    if (i < E) atomicAdd(&g_deg[dst[i]], 1);
}

// per-block totals into g_bsum
__global__ void k_scan_a(int N) {
    int idx = blockIdx.x * 1024 + threadIdx.x;
    int v = (idx < N) ? g_deg[idx] : 0;
    #pragma unroll
    for (int d = 16; d > 0; d >>= 1) v += __shfl_down_sync(0xffffffffu, v, d);
    __shared__ int ws[32];
    if ((threadIdx.x & 31) == 0) ws[threadIdx.x >> 5] = v;
    __syncthreads();
    if (threadIdx.x < 32) {
        int s = ws[threadIdx.x];
        #pragma unroll
        for (int d = 16; d > 0; d >>= 1) s += __shfl_down_sync(0xffffffffu, s, d);
        if (threadIdx.x == 0) g_bsum[blockIdx.x] = s;
    }
}

// block-local scan + inline prefix over g_bsum (nb <= 64, so 2 warps cover it)
__global__ void k_scan_c(int N) {
    int idx = blockIdx.x * 1024 + threadIdx.x;
    int lane = threadIdx.x & 31, wid = threadIdx.x >> 5;
    __shared__ int partial[2];
    if (threadIdx.x < 64) {
        int v = (threadIdx.x < blockIdx.x) ? g_bsum[threadIdx.x] : 0;
        #pragma unroll
        for (int d = 16; d > 0; d >>= 1) v += __shfl_down_sync(0xffffffffu, v, d);
        if (lane == 0) partial[wid] = v;
    }
    int v = (idx < N) ? g_deg[idx] : 0;
    int val = v;
    #pragma unroll
    for (int d = 1; d < 32; d <<= 1) {
        int t = __shfl_up_sync(0xffffffffu, val, d);
        if (lane >= d) val += t;
    }
    __shared__ int ws[32];
    if (lane == 31) ws[wid] = val;
    __syncthreads();
    int blockbase = partial[0] + partial[1];
    if (wid == 0) {
        int s = ws[lane];
        #pragma unroll
        for (int d = 1; d < 32; d <<= 1) {
            int t = __shfl_up_sync(0xffffffffu, s, d);
            if (lane >= d) s += t;
        }
        ws[lane] = s;
    }
    __syncthreads();
    int base = blockbase + (wid ? ws[wid - 1] : 0);
    int excl = base + val - v;
    if (idx < N) { g_off[idx] = excl; g_cur[idx] = excl; }
    if (idx == N - 1) g_off[N] = excl + v;
}

__global__ void k_scatter(const int* __restrict__ src, const int* __restrict__ dst, int E) {
    int i = blockIdx.x * blockDim.x + threadIdx.x;
    if (i < E) {
        int pos = atomicAdd(&g_cur[dst[i]], 1);
        g_ssrc[pos] = src[i];
    }
}

// ---------------- Node transform: P = h@(W1a-W1b)+b1, Q = h@W1b (stored fp16) ----------------

__global__ void k_node(const float* __restrict__ x, const float* __restrict__ sc,
                       const int* __restrict__ batch, const float* __restrict__ W1,
                       const float* __restrict__ b1, int N) {
    extern __shared__ char smem[];
    u64* Wdp = (u64*)smem;                 // 34*128 packed k-pairs of (W1a - W1b)
    u64* Wbp = Wdp + 34 * 128;             // 34*128 packed k-pairs of W1b
    float* hs = (float*)(Wbp + 34 * 128);  // 8 nodes * 68 feats
    float* b1s = hs + 8 * 68;              // 128
    int tid = threadIdx.x;                 // 128 threads

    for (int i = tid; i < 34 * 128; i += 128) {
        int kp = i >> 7, c = i & 127;
        float a0 = W1[(2 * kp) * 128 + c];
        float a1 = W1[(2 * kp + 1) * 128 + c];
        float q0 = W1[(68 + 2 * kp) * 128 + c];
        float q1 = W1[(68 + 2 * kp + 1) * 128 + c];
        Wdp[i] = pack2f(a0 - q0, a1 - q1);
        Wbp[i] = pack2f(q0, q1);
    }
    b1s[tid] = b1[tid];
    __syncthreads();

    int c = tid;
    int ntiles = (N + 7) >> 3;
    for (int tile = blockIdx.x; tile < ntiles; tile += gridDim.x) {
        int n0 = tile << 3;
        for (int i = tid; i < 8 * 68; i += 128) {
            int nn = i / 68, k = i - nn * 68;
            int n = n0 + nn;
            float v = 0.f;
            if (n < N) v = (k < 64) ? x[(size_t)n * 64 + k] : sc[batch[n] * 4 + (k - 64)];
            hs[i] = v;
        }
        __syncthreads();
        u64 accP[8], accQ[8];
        #pragma unroll
        for (int nn = 0; nn < 8; ++nn) {
            accP[nn] = pack2f(b1s[c], 0.f);
            accQ[nn] = pack2f(0.f, 0.f);
        }
        #pragma unroll
        for (int k = 0; k < 68; k += 4) {
            int kp = k >> 1;
            u64 wd0 = Wdp[kp * 128 + c], wd1 = Wdp[(kp + 1) * 128 + c];
            u64 wb0 = Wbp[kp * 128 + c], wb1 = Wbp[(kp + 1) * 128 + c];
            #pragma unroll
            for (int nn = 0; nn < 8; ++nn) {
                ulonglong2 hh = *(const ulonglong2*)(hs + nn * 68 + k);
                accP[nn] = ffma2(wd0, hh.x, accP[nn]);
                accQ[nn] = ffma2(wb0, hh.x, accQ[nn]);
                accP[nn] = ffma2(wd1, hh.y, accP[nn]);
                accQ[nn] = ffma2(wb1, hh.y, accQ[nn]);
            }
        }
        #pragma unroll
        for (int nn = 0; nn < 8; ++nn) {
            int n = n0 + nn;
            if (n < N) {
                float2 fp = unpack2f(accP[nn]);
                float2 fq = unpack2f(accQ[nn]);
                g_Ph[(size_t)n * 128 + c] = __float2half_rn(fp.x + fp.y);
                g_Qh[(size_t)n * 128 + c] = __float2half_rn(fq.x + fq.y);
            }
        }
        __syncthreads();
    }
}

// ---------------- Edge aggregation: H[n] = sum_{e:dst=n} relu(P[n] + Q[src_e]) ----------------
// One warp per node; lane l owns cols 4l..4l+3 as 2x half2. fp16 gather (256B/edge), fp32 accum.

__global__ void k_edge(int N) {
    int gw = (blockIdx.x * blockDim.x + threadIdx.x) >> 5;
    int lane = threadIdx.x & 31;
    if (gw >= N) return;
    int beg = g_off[gw], end = g_off[gw + 1];
    uint2 pp = *(const uint2*)(g_Ph + (size_t)gw * 128 + lane * 4);
    __half2 p0 = *(__half2*)&pp.x;
    __half2 p1 = *(__half2*)&pp.y;
    const __half2 z2 = __floats2half2_rn(0.f, 0.f);
    float4 acc = make_float4(0.f, 0.f, 0.f, 0.f);
    for (int base = beg; base < end; base += 32) {
        int m = end - base; if (m > 32) m = 32;
        int myj = (lane < m) ? __ldg(&g_ssrc[base + lane]) : 0;
        if (m == 32) {
            #pragma unroll 4
            for (int t = 0; t < 32; ++t) {
                int j = __shfl_sync(0xffffffffu, myj, t);
                uint2 qq = *(const uint2*)(g_Qh + (size_t)j * 128 + lane * 4);
                __half2 s0 = __hmax2(__hadd2(p0, *(__half2*)&qq.x), z2);
                __half2 s1 = __hmax2(__hadd2(p1, *(__half2*)&qq.y), z2);
                float2 f0 = __half22float2(s0);
                float2 f1 = __half22float2(s1);
                acc.x += f0.x; acc.y += f0.y;
                acc.z += f1.x; acc.w += f1.y;
            }
        } else {
            for (int t = 0; t < m; ++t) {
                int j = __shfl_sync(0xffffffffu, myj, t);
                uint2 qq = *(const uint2*)(g_Qh + (size_t)j * 128 + lane * 4);
                __half2 s0 = __hmax2(__hadd2(p0, *(__half2*)&qq.x), z2);
                __half2 s1 = __hmax2(__hadd2(p1, *(__half2*)&qq.y), z2);
                float2 f0 = __half22float2(s0);
                float2 f1 = __half22float2(s1);
                acc.x += f0.x; acc.y += f0.y;
                acc.z += f1.x; acc.w += f1.y;
            }
        }
    }
    *(float4*)(g_H + (size_t)gw * 128 + lane * 4) = acc;
}

// ---------------- Output GEMM: out = H @ W2 + deg*b2 (16-node tiles) ----------------

__global__ void k_out(const float* __restrict__ W2, const float* __restrict__ b2,
                      float* __restrict__ out, int N) {
    extern __shared__ char smem[];
    u64* W2p = (u64*)smem;                  // 64*128 packed k-pairs
    float* hs = (float*)(W2p + 64 * 128);   // 16 nodes * 128
    float* b2s = hs + 16 * 128;             // 128
    int tid = threadIdx.x;                  // 128 threads

    for (int i = tid; i < 64 * 128; i += 128) {
        int kp = i >> 7, c = i & 127;
        W2p[i] = pack2f(W2[(2 * kp) * 128 + c], W2[(2 * kp + 1) * 128 + c]);
    }
    b2s[tid] = b2[tid];
    __syncthreads();

    int c = tid;
    int ntiles = (N + 15) >> 4;
    for (int tile = blockIdx.x; tile < ntiles; tile += gridDim.x) {
        int n0 = tile << 4;
        for (int i = tid; i < 16 * 128; i += 128) {
            int nn = i >> 7, cc = i & 127;
            int n = n0 + nn;
            hs[i] = (n < N) ? g_H[(size_t)n * 128 + cc] : 0.f;
        }
        __syncthreads();
        u64 acc[16];
        #pragma unroll
        for (int nn = 0; nn < 16; ++nn) acc[nn] = pack2f(0.f, 0.f);
        #pragma unroll 8
        for (int k = 0; k < 128; k += 4) {
            int kp = k >> 1;
            u64 w0 = W2p[kp * 128 + c], w1 = W2p[(kp + 1) * 128 + c];
            #pragma unroll
            for (int nn = 0; nn < 16; ++nn) {
                ulonglong2 hh = *(const ulonglong2*)(hs + nn * 128 + k);
                acc[nn] = ffma2(w0, hh.x, acc[nn]);
                acc[nn] = ffma2(w1, hh.y, acc[nn]);
            }
        }
        #pragma unroll
        for (int nn = 0; nn < 16; ++nn) {
            int n = n0 + nn;
            if (n < N) {
                float2 f = unpack2f(acc[nn]);
                float deg = (float)(g_off[n + 1] - g_off[n]);
                out[(size_t)n * 128 + c] = f.x + f.y + deg * b2s[c];
            }
        }
        __syncthreads();
    }
}

// ---------------- launch ----------------

extern "C" void kernel_launch(void* const* d_in, const int* in_sizes, int n_in,
                              void* d_out, int out_size) {
    const float* x   = (const float*)d_in[0];
    const float* sc  = (const float*)d_in[1];
    const int* batch = (const int*)d_in[2];
    const int* ei    = (const int*)d_in[3];
    const float* W1  = (const float*)d_in[4];
    const float* b1  = (const float*)d_in[5];
    const float* W2  = (const float*)d_in[6];
    const float* b2  = (const float*)d_in[7];
    float* out = (float*)d_out;
    int N = in_sizes[0] / 64;
    int E = in_sizes[3] / 2;
    const int* src = ei;        // edge_index[0]
    const int* dst = ei + E;    // edge_index[1]

    const int smem_node = 2 * 34 * 128 * 8 + 8 * 68 * 4 + 128 * 4;    // 72320 B
    const int smem_out  = 64 * 128 * 8 + 16 * 128 * 4 + 128 * 4;      // 74240 B
    cudaFuncSetAttribute(k_node, cudaFuncAttributeMaxDynamicSharedMemorySize, smem_node);
    cudaFuncSetAttribute(k_out,  cudaFuncAttributeMaxDynamicSharedMemorySize, smem_out);

    void* degp = 0;
    cudaGetSymbolAddress(&degp, g_deg);
    cudaMemsetAsync(degp, 0, (size_t)N * sizeof(int));

    int nb = (N + 1023) >> 10;
    k_hist<<<(E + 255) / 256, 256>>>(dst, E);
    k_scan_a<<<nb, 1024>>>(N);
    k_scan_c<<<nb, 1024>>>(N);
    k_scatter<<<(E + 255) / 256, 256>>>(src, dst, E);
    k_node<<<296, 128, smem_node>>>(x, sc, batch, W1, b1, N);
    k_edge<<<(N + 7) / 8, 256>>>(N);
    k_out<<<444, 128, smem_out>>>(W2, b2, out, N);
}

// round 8
// speedup vs baseline: 1.1039x; 1.0584x over previous
#include <cuda_runtime.h>
#include <cuda_fp16.h>

typedef unsigned long long u64;

#define NMAX 50048
#define EMAX 1600000

__device__ int    g_deg[NMAX];
__device__ int    g_off[NMAX + 1];
__device__ int    g_cur[NMAX];
__device__ int    g_bsum[64];
__device__ int    g_ssrc[EMAX];
__device__ __half g_Ph[(size_t)NMAX * 128];
__device__ __half g_Qh[(size_t)NMAX * 128];
__device__ float  g_H[(size_t)NMAX * 128];

__device__ __forceinline__ u64 pack2f(float lo, float hi) {
    u64 r; asm("mov.b64 %0, {%1, %2};" : "=l"(r) : "f"(lo), "f"(hi)); return r;
}
__device__ __forceinline__ float2 unpack2f(u64 v) {
    float2 f; asm("mov.b64 {%0, %1}, %2;" : "=f"(f.x), "=f"(f.y) : "l"(v)); return f;
}
__device__ __forceinline__ u64 ffma2(u64 a, u64 b, u64 c) {
    u64 d; asm("fma.rn.f32x2 %0, %1, %2, %3;" : "=l"(d) : "l"(a), "l"(b), "l"(c)); return d;
}

// ---------------- CSR build ----------------

// 4 edges per thread -> 4 independent in-flight ATOMGs (latency hiding)
__global__ void k_hist(const int* __restrict__ dst, int E) {
    int i0 = (blockIdx.x * blockDim.x + threadIdx.x) * 4;
    if (i0 + 3 < E) {
        int4 d = *(const int4*)(dst + i0);
        atomicAdd(&g_deg[d.x], 1);
        atomicAdd(&g_deg[d.y], 1);
        atomicAdd(&g_deg[d.z], 1);
        atomicAdd(&g_deg[d.w], 1);
    } else {
        for (int i = i0; i < E; ++i) atomicAdd(&g_deg[dst[i]], 1);
    }
}

// per-block totals into g_bsum
__global__ void k_scan_a(int N) {
    int idx = blockIdx.x * 1024 + threadIdx.x;
    int v = (idx < N) ? g_deg[idx] : 0;
    #pragma unroll
    for (int d = 16; d > 0; d >>= 1) v += __shfl_down_sync(0xffffffffu, v, d);
    __shared__ int ws[32];
    if ((threadIdx.x & 31) == 0) ws[threadIdx.x >> 5] = v;
    __syncthreads();
    if (threadIdx.x < 32) {
        int s = ws[threadIdx.x];
        #pragma unroll
        for (int d = 16; d > 0; d >>= 1) s += __shfl_down_sync(0xffffffffu, s, d);
        if (threadIdx.x == 0) g_bsum[blockIdx.x] = s;
    }
}

// block-local scan + inline prefix over g_bsum (nb <= 64, so 2 warps cover it)
__global__ void k_scan_c(int N) {
    int idx = blockIdx.x * 1024 + threadIdx.x;
    int lane = threadIdx.x & 31, wid = threadIdx.x >> 5;
    __shared__ int partial[2];
    if (threadIdx.x < 64) {
        int v = (threadIdx.x < blockIdx.x) ? g_bsum[threadIdx.x] : 0;
        #pragma unroll
        for (int d = 16; d > 0; d >>= 1) v += __shfl_down_sync(0xffffffffu, v, d);
        if (lane == 0) partial[wid] = v;
    }
    int v = (idx < N) ? g_deg[idx] : 0;
    int val = v;
    #pragma unroll
    for (int d = 1; d < 32; d <<= 1) {
        int t = __shfl_up_sync(0xffffffffu, val, d);
        if (lane >= d) val += t;
    }
    __shared__ int ws[32];
    if (lane == 31) ws[wid] = val;
    __syncthreads();
    int blockbase = partial[0] + partial[1];
    if (wid == 0) {
        int s = ws[lane];
        #pragma unroll
        for (int d = 1; d < 32; d <<= 1) {
            int t = __shfl_up_sync(0xffffffffu, s, d);
            if (lane >= d) s += t;
        }
        ws[lane] = s;
    }
    __syncthreads();
    int base = blockbase + (wid ? ws[wid - 1] : 0);
    int excl = base + val - v;
    if (idx < N) { g_off[idx] = excl; g_cur[idx] = excl; }
    if (idx == N - 1) g_off[N] = excl + v;
}

// 4 edges per thread -> 4 independent atomic+store chains
__global__ void k_scatter(const int* __restrict__ src, const int* __restrict__ dst, int E) {
    int i0 = (blockIdx.x * blockDim.x + threadIdx.x) * 4;
    if (i0 + 3 < E) {
        int4 d = *(const int4*)(dst + i0);
        int4 s = *(const int4*)(src + i0);
        int p0 = atomicAdd(&g_cur[d.x], 1);
        int p1 = atomicAdd(&g_cur[d.y], 1);
        int p2 = atomicAdd(&g_cur[d.z], 1);
        int p3 = atomicAdd(&g_cur[d.w], 1);
        g_ssrc[p0] = s.x;
        g_ssrc[p1] = s.y;
        g_ssrc[p2] = s.z;
        g_ssrc[p3] = s.w;
    } else {
        for (int i = i0; i < E; ++i) {
            int pos = atomicAdd(&g_cur[dst[i]], 1);
            g_ssrc[pos] = src[i];
        }
    }
}

// ---------------- Node transform: P = h@(W1a-W1b)+b1, Q = h@W1b (stored fp16) ----------------

__global__ void k_node(const float* __restrict__ x, const float* __restrict__ sc,
                       const int* __restrict__ batch, const float* __restrict__ W1,
                       const float* __restrict__ b1, int N) {
    extern __shared__ char smem[];
    u64* Wdp = (u64*)smem;                 // 34*128 packed k-pairs of (W1a - W1b)
    u64* Wbp = Wdp + 34 * 128;             // 34*128 packed k-pairs of W1b
    float* hs = (float*)(Wbp + 34 * 128);  // 8 nodes * 68 feats
    float* b1s = hs + 8 * 68;              // 128
    int tid = threadIdx.x;                 // 128 threads

    for (int i = tid; i < 34 * 128; i += 128) {
        int kp = i >> 7, c = i & 127;
        float a0 = W1[(2 * kp) * 128 + c];
        float a1 = W1[(2 * kp + 1) * 128 + c];
        float q0 = W1[(68 + 2 * kp) * 128 + c];
        float q1 = W1[(68 + 2 * kp + 1) * 128 + c];
        Wdp[i] = pack2f(a0 - q0, a1 - q1);
        Wbp[i] = pack2f(q0, q1);
    }
    b1s[tid] = b1[tid];
    __syncthreads();

    int c = tid;
    int ntiles = (N + 7) >> 3;
    for (int tile = blockIdx.x; tile < ntiles; tile += gridDim.x) {
        int n0 = tile << 3;
        for (int i = tid; i < 8 * 68; i += 128) {
            int nn = i / 68, k = i - nn * 68;
            int n = n0 + nn;
            float v = 0.f;
            if (n < N) v = (k < 64) ? x[(size_t)n * 64 + k] : sc[batch[n] * 4 + (k - 64)];
            hs[i] = v;
        }
        __syncthreads();
        u64 accP[8], accQ[8];
        #pragma unroll
        for (int nn = 0; nn < 8; ++nn) {
            accP[nn] = pack2f(b1s[c], 0.f);
            accQ[nn] = pack2f(0.f, 0.f);
        }
        #pragma unroll
        for (int k = 0; k < 68; k += 4) {
            int kp = k >> 1;
            u64 wd0 = Wdp[kp * 128 + c], wd1 = Wdp[(kp + 1) * 128 + c];
            u64 wb0 = Wbp[kp * 128 + c], wb1 = Wbp[(kp + 1) * 128 + c];
            #pragma unroll
            for (int nn = 0; nn < 8; ++nn) {
                ulonglong2 hh = *(const ulonglong2*)(hs + nn * 68 + k);
                accP[nn] = ffma2(wd0, hh.x, accP[nn]);
                accQ[nn] = ffma2(wb0, hh.x, accQ[nn]);
                accP[nn] = ffma2(wd1, hh.y, accP[nn]);
                accQ[nn] = ffma2(wb1, hh.y, accQ[nn]);
            }
        }
        #pragma unroll
        for (int nn = 0; nn < 8; ++nn) {
            int n = n0 + nn;
            if (n < N) {
                float2 fp = unpack2f(accP[nn]);
                float2 fq = unpack2f(accQ[nn]);
                g_Ph[(size_t)n * 128 + c] = __float2half_rn(fp.x + fp.y);
                g_Qh[(size_t)n * 128 + c] = __float2half_rn(fq.x + fq.y);
            }
        }
        __syncthreads();
    }
}

// ---------------- Edge aggregation: H[n] = sum_{e:dst=n} relu(P[n] + Q[src_e]) ----------------

__global__ void k_edge(int N) {
    int gw = (blockIdx.x * blockDim.x + threadIdx.x) >> 5;
    int lane = threadIdx.x & 31;
    if (gw >= N) return;
    int beg = g_off[gw], end = g_off[gw + 1];
    uint2 pp = *(const uint2*)(g_Ph + (size_t)gw * 128 + lane * 4);
    __half2 p0 = *(__half2*)&pp.x;
    __half2 p1 = *(__half2*)&pp.y;
    const __half2 z2 = __floats2half2_rn(0.f, 0.f);
    float4 acc = make_float4(0.f, 0.f, 0.f, 0.f);
    for (int base = beg; base < end; base += 32) {
        int m = end - base; if (m > 32) m = 32;
        int myj = (lane < m) ? __ldg(&g_ssrc[base + lane]) : 0;
        if (m == 32) {
            #pragma unroll 4
            for (int t = 0; t < 32; ++t) {
                int j = __shfl_sync(0xffffffffu, myj, t);
                uint2 qq = *(const uint2*)(g_Qh + (size_t)j * 128 + lane * 4);
                __half2 s0 = __hmax2(__hadd2(p0, *(__half2*)&qq.x), z2);
                __half2 s1 = __hmax2(__hadd2(p1, *(__half2*)&qq.y), z2);
                float2 f0 = __half22float2(s0);
                float2 f1 = __half22float2(s1);
                acc.x += f0.x; acc.y += f0.y;
                acc.z += f1.x; acc.w += f1.y;
            }
        } else {
            for (int t = 0; t < m; ++t) {
                int j = __shfl_sync(0xffffffffu, myj, t);
                uint2 qq = *(const uint2*)(g_Qh + (size_t)j * 128 + lane * 4);
                __half2 s0 = __hmax2(__hadd2(p0, *(__half2*)&qq.x), z2);
                __half2 s1 = __hmax2(__hadd2(p1, *(__half2*)&qq.y), z2);
                float2 f0 = __half22float2(s0);
                float2 f1 = __half22float2(s1);
                acc.x += f0.x; acc.y += f0.y;
                acc.z += f1.x; acc.w += f1.y;
            }
        }
    }
    *(float4*)(g_H + (size_t)gw * 128 + lane * 4) = acc;
}

// ---------------- Output GEMM: out = H @ W2 + deg*b2 (16-node tiles) ----------------

__global__ void k_out(const float* __restrict__ W2, const float* __restrict__ b2,
                      float* __restrict__ out, int N) {
    extern __shared__ char smem[];
    u64* W2p = (u64*)smem;                  // 64*128 packed k-pairs
    float* hs = (float*)(W2p + 64 * 128);   // 16 nodes * 128
    float* b2s = hs + 16 * 128;             // 128
    int tid = threadIdx.x;                  // 128 threads

    for (int i = tid; i < 64 * 128; i += 128) {
        int kp = i >> 7, c = i & 127;
        W2p[i] = pack2f(W2[(2 * kp) * 128 + c], W2[(2 * kp + 1) * 128 + c]);
    }
    b2s[tid] = b2[tid];
    __syncthreads();

    int c = tid;
    int ntiles = (N + 15) >> 4;
    for (int tile = blockIdx.x; tile < ntiles; tile += gridDim.x) {
        int n0 = tile << 4;
        for (int i = tid; i < 16 * 128; i += 128) {
            int nn = i >> 7, cc = i & 127;
            int n = n0 + nn;
            hs[i] = (n < N) ? g_H[(size_t)n * 128 + cc] : 0.f;
        }
        __syncthreads();
        u64 acc[16];
        #pragma unroll
        for (int nn = 0; nn < 16; ++nn) acc[nn] = pack2f(0.f, 0.f);
        #pragma unroll 8
        for (int k = 0; k < 128; k += 4) {
            int kp = k >> 1;
            u64 w0 = W2p[kp * 128 + c], w1 = W2p[(kp + 1) * 128 + c];
            #pragma unroll
            for (int nn = 0; nn < 16; ++nn) {
                ulonglong2 hh = *(const ulonglong2*)(hs + nn * 128 + k);
                acc[nn] = ffma2(w0, hh.x, acc[nn]);
                acc[nn] = ffma2(w1, hh.y, acc[nn]);
            }
        }
        #pragma unroll
        for (int nn = 0; nn < 16; ++nn) {
            int n = n0 + nn;
            if (n < N) {
                float2 f = unpack2f(acc[nn]);
                float deg = (float)(g_off[n + 1] - g_off[n]);
                out[(size_t)n * 128 + c] = f.x + f.y + deg * b2s[c];
            }
        }
        __syncthreads();
    }
}

// ---------------- launch ----------------

extern "C" void kernel_launch(void* const* d_in, const int* in_sizes, int n_in,
                              void* d_out, int out_size) {
    const float* x   = (const float*)d_in[0];
    const float* sc  = (const float*)d_in[1];
    const int* batch = (const int*)d_in[2];
    const int* ei    = (const int*)d_in[3];
    const float* W1  = (const float*)d_in[4];
    const float* b1  = (const float*)d_in[5];
    const float* W2  = (const float*)d_in[6];
    const float* b2  = (const float*)d_in[7];
    float* out = (float*)d_out;
    int N = in_sizes[0] / 64;
    int E = in_sizes[3] / 2;
    const int* src = ei;        // edge_index[0]
    const int* dst = ei + E;    // edge_index[1]

    const int smem_node = 2 * 34 * 128 * 8 + 8 * 68 * 4 + 128 * 4;    // 72320 B
    const int smem_out  = 64 * 128 * 8 + 16 * 128 * 4 + 128 * 4;      // 74240 B

    // One-time infra (created on the first, non-captured correctness call;
    // reused identically on every call -> deterministic work).
    static bool inited = false;
    static cudaStream_t s2;
    static cudaEvent_t evFork, evJoin;
    if (!inited) {
        cudaFuncSetAttribute(k_node, cudaFuncAttributeMaxDynamicSharedMemorySize, smem_node);
        cudaFuncSetAttribute(k_out,  cudaFuncAttributeMaxDynamicSharedMemorySize, smem_out);
        cudaStreamCreateWithFlags(&s2, cudaStreamNonBlocking);
        cudaEventCreateWithFlags(&evFork, cudaEventDisableTiming);
        cudaEventCreateWithFlags(&evJoin, cudaEventDisableTiming);
        inited = true;
    }

    void* degp = 0;
    cudaGetSymbolAddress(&degp, g_deg);

    // Fork: k_node (weights/features only) runs concurrently with the CSR build.
    cudaEventRecord(evFork, 0);
    cudaStreamWaitEvent(s2, evFork, 0);
    k_node<<<296, 128, smem_node, s2>>>(x, sc, batch, W1, b1, N);
    cudaEventRecord(evJoin, s2);

    // CSR chain on the main stream.
    cudaMemsetAsync(degp, 0, (size_t)N * sizeof(int));
    int nb = (N + 1023) >> 10;
    k_hist<<<(E / 4 + 255) / 256, 256>>>(dst, E);
    k_scan_a<<<nb, 1024>>>(N);
    k_scan_c<<<nb, 1024>>>(N);
    k_scatter<<<(E / 4 + 255) / 256, 256>>>(src, dst, E);

    // Join: k_edge needs both CSR and P/Q.
    cudaStreamWaitEvent(0, evJoin, 0);
    k_edge<<<(N + 7) / 8, 256>>>(N);
    k_out<<<444, 128, smem_out>>>(W2, b2, out, N);
}